// round 6
// baseline (speedup 1.0000x reference)
#include <cuda_runtime.h>
#include <cuda_bf16.h>
#include <cstdint>

// Problem dims (fixed): B=4, N=2048, F_in=128, H=4, D=32
#define Bn 4
#define Nn 2048
#define Fn 128
#define Hn 4
#define Dn 32
#define BH (Bn*Hn)

// Scratch (device globals; no allocation allowed). 16B+ alignment for float4 access.
__device__ __align__(256) float g_Wh[BH * Nn * Dn];   // [bh][n][d]  4 MB
__device__ __align__(16)  float g_es[BH * Nn];        // e_src
__device__ __align__(16)  float g_ed[BH * Nn];        // e_dst

// -------------------- Kernel A: projection + e_src/e_dst --------------------
__global__ __launch_bounds__(128) void proj_kernel(
    const float* __restrict__ h, const float* __restrict__ W,
    const float* __restrict__ a)
{
    __shared__ __align__(16) float h_sm[16 * Fn];
    const int b  = blockIdx.x;
    const int n0 = blockIdx.y * 16;

    const float4* hsrc = (const float4*)(h + (size_t)(b * Nn + n0) * Fn);
    float4* hdst = (float4*)h_sm;
    #pragma unroll
    for (int r = 0; r < 4; r++) hdst[threadIdx.x + r * 128] = hsrc[threadIdx.x + r * 128];
    __syncthreads();

    const int warp = threadIdx.x >> 5;   // head
    const int lane = threadIdx.x & 31;   // d

    const float* Wp = W + (warp * Fn) * Dn + lane;
    float acc[16];
    #pragma unroll
    for (int n = 0; n < 16; n++) acc[n] = 0.f;

    #pragma unroll 4
    for (int f = 0; f < Fn; f++) {
        float w = __ldg(Wp + f * Dn);
        #pragma unroll
        for (int n = 0; n < 16; n++)
            acc[n] = fmaf(h_sm[n * Fn + f], w, acc[n]);
    }

    const float a_s = __ldg(a + warp * (2 * Dn) + lane);
    const float a_d = __ldg(a + warp * (2 * Dn) + Dn + lane);

    const int bh = b * Hn + warp;
    float* whp = g_Wh + ((size_t)bh * Nn + n0) * Dn + lane;

    #pragma unroll
    for (int n = 0; n < 16; n++) {
        whp[n * Dn] = acc[n];
        float es = acc[n] * a_s;
        float ed = acc[n] * a_d;
        #pragma unroll
        for (int off = 16; off; off >>= 1) {
            es += __shfl_xor_sync(0xffffffffu, es, off);
            ed += __shfl_xor_sync(0xffffffffu, ed, off);
        }
        if (lane == 0) {
            g_es[bh * Nn + n0 + n] = es;
            g_ed[bh * Nn + n0 + n] = ed;
        }
    }
}

// -------------------- Kernel B: masked-softmax (exact row max) + P@Wh --------------------
// 256 threads = 8 warps; warp owns 4 rows. Lane = (dh, jh): dh = lane>>4 picks d-half
// [dh*16, dh*16+16), jh = lane&15 picks j ≡ jh (mod 16). Each 128B wh smem read now
// serves 4 rows (was 2) -> half the LDS traffic per FMA.
#define TJ 128
#define WPAD 36
#define FULLM 0xffffffffu

#define FMA16(V, P, W0, W1, W2, W3)                        \
    V[0]  = fmaf(P, W0.x, V[0]);  V[1]  = fmaf(P, W0.y, V[1]);   \
    V[2]  = fmaf(P, W0.z, V[2]);  V[3]  = fmaf(P, W0.w, V[3]);   \
    V[4]  = fmaf(P, W1.x, V[4]);  V[5]  = fmaf(P, W1.y, V[5]);   \
    V[6]  = fmaf(P, W1.z, V[6]);  V[7]  = fmaf(P, W1.w, V[7]);   \
    V[8]  = fmaf(P, W2.x, V[8]);  V[9]  = fmaf(P, W2.y, V[9]);   \
    V[10] = fmaf(P, W2.z, V[10]); V[11] = fmaf(P, W2.w, V[11]);  \
    V[12] = fmaf(P, W3.x, V[12]); V[13] = fmaf(P, W3.y, V[13]);  \
    V[14] = fmaf(P, W3.z, V[14]); V[15] = fmaf(P, W3.w, V[15]);

__global__ __launch_bounds__(256, 2) void attn_kernel(
    const int* __restrict__ adj, float* __restrict__ out)
{
    __shared__ __align__(16) float ed_full[Nn];        // 8 KB
    __shared__ __align__(16) float wh_sm[TJ * WPAD];   // 18 KB

    const int bh = blockIdx.x;
    const int b  = bh >> 2;
    const int hd = bh & 3;
    const int warp = threadIdx.x >> 5;
    const int lane = threadIdx.x & 31;
    const int jh = lane & 15;
    const int dh = lane >> 4;
    const int base = blockIdx.y * 32 + warp * 4;   // first of this warp's 4 rows

    // stage full e_dst row (2048 floats)
    {
        const float4* src = (const float4*)(g_ed + bh * Nn);
        float4* dst = (float4*)ed_full;
        #pragma unroll
        for (int r = 0; r < 2; r++) dst[threadIdx.x + r * 256] = src[threadIdx.x + r * 256];
    }
    __syncthreads();

    // ---- Pass 1: masked row max + adjacency bit-pack ----
    // half dh scans rows base+2*dh and base+2*dh+1; bits exchanged by shuffle after.
    const int rA = base + dh * 2;
    const int rB = rA + 1;
    const int* adjA = adj + (size_t)rA * Nn;
    const int* adjB = adj + (size_t)rB * Nn;
    uint32_t mA[4], mB[4];
    float mxA = -1e30f, mxB = -1e30f;
    #pragma unroll
    for (int w = 0; w < 4; w++) {
        uint32_t ma = 0, mb = 0;
        #pragma unroll 8
        for (int bit = 0; bit < 32; bit++) {
            const int j = (((w << 5) + bit) << 4) + jh;
            const float ed = ed_full[j];
            if (__ldg(adjA + j) > 0) { mxA = fmaxf(mxA, ed); ma |= 1u << bit; }
            if (__ldg(adjB + j) > 0) { mxB = fmaxf(mxB, ed); mb |= 1u << bit; }
        }
        mA[w] = ma; mB[w] = mb;
    }
    // reduce maxes within each 16-lane half
    #pragma unroll
    for (int off = 8; off; off >>= 1) {
        mxA = fmaxf(mxA, __shfl_xor_sync(FULLM, mxA, off));
        mxB = fmaxf(mxB, __shfl_xor_sync(FULLM, mxB, off));
    }
    // distribute: row r masks/maxes to every lane (at its own jh)
    const float mx0 = __shfl_sync(FULLM, mxA, jh);
    const float mx1 = __shfl_sync(FULLM, mxB, jh);
    const float mx2 = __shfl_sync(FULLM, mxA, jh + 16);
    const float mx3 = __shfl_sync(FULLM, mxB, jh + 16);
    uint32_t b0[4], b1[4], b2[4], b3[4];
    #pragma unroll
    for (int k = 0; k < 4; k++) {
        b0[k] = __shfl_sync(FULLM, mA[k], jh);
        b1[k] = __shfl_sync(FULLM, mB[k], jh);
        b2[k] = __shfl_sync(FULLM, mA[k], jh + 16);
        b3[k] = __shfl_sync(FULLM, mB[k], jh + 16);
    }

    const float es0 = __ldg(g_es + bh * Nn + base + 0);
    const float es1 = __ldg(g_es + bh * Nn + base + 1);
    const float es2 = __ldg(g_es + bh * Nn + base + 2);
    const float es3 = __ldg(g_es + bh * Nn + base + 3);

    const float nz0 = (mx0 < -9e29f) ? 1.f : 0.f;   // empty row -> uniform (matches ref)
    const float nz1 = (mx1 < -9e29f) ? 1.f : 0.f;
    const float nz2 = (mx2 < -9e29f) ? 1.f : 0.f;
    const float nz3 = (mx3 < -9e29f) ? 1.f : 0.f;
    float M0 = es0 + mx0; M0 = fmaxf(M0, 0.2f * M0); if (nz0 > 0.f) M0 = 0.f;
    float M1 = es1 + mx1; M1 = fmaxf(M1, 0.2f * M1); if (nz1 > 0.f) M1 = 0.f;
    float M2 = es2 + mx2; M2 = fmaxf(M2, 0.2f * M2); if (nz2 > 0.f) M2 = 0.f;
    float M3 = es3 + mx3; M3 = fmaxf(M3, 0.2f * M3); if (nz3 > 0.f) M3 = 0.f;

    // ---- Pass 2: exp + P@Wh ----
    float v0[16], v1[16], v2[16], v3[16];
    #pragma unroll
    for (int k = 0; k < 16; k++) { v0[k] = 0.f; v1[k] = 0.f; v2[k] = 0.f; v3[k] = 0.f; }
    float l0 = 0.f, l1 = 0.f, l2 = 0.f, l3 = 0.f;

    const float* whg = g_Wh + (size_t)bh * Nn * Dn;
    const int dofs = dh << 4;

    #pragma unroll
    for (int cw = 0; cw < 4; cw++) {
        const uint32_t B0 = b0[cw], B1 = b1[cw], B2 = b2[cw], B3 = b3[cw];
        for (int cc = 0; cc < 4; cc++) {
            const int c  = (cw << 2) + cc;
            const int jb = c * TJ;
            __syncthreads();
            #pragma unroll
            for (int r = 0; r < 4; r++) {
                int i4  = threadIdx.x + r * 256;
                int row = i4 >> 3;
                int c4  = i4 & 7;
                float4 val = *(const float4*)(whg + (size_t)(jb + row) * Dn + c4 * 4);
                *(float4*)(wh_sm + row * WPAD + c4 * 4) = val;
            }
            __syncthreads();

            #pragma unroll
            for (int t = 0; t < 4; t++) {
                #pragma unroll
                for (int jj = 0; jj < 2; jj++) {
                    const int ridx = t * 32 + jj * 16 + jh;
                    const int bi   = cc * 8 + t * 2 + jj;
                    const float ed = ed_full[jb + ridx];
                    float s0 = es0 + ed; s0 = fmaxf(s0, 0.2f * s0);
                    float s1 = es1 + ed; s1 = fmaxf(s1, 0.2f * s1);
                    float s2 = es2 + ed; s2 = fmaxf(s2, 0.2f * s2);
                    float s3 = es3 + ed; s3 = fmaxf(s3, 0.2f * s3);
                    const float p0 = ((B0 >> bi) & 1u) ? __expf(s0 - M0) : nz0;
                    const float p1 = ((B1 >> bi) & 1u) ? __expf(s1 - M1) : nz1;
                    const float p2 = ((B2 >> bi) & 1u) ? __expf(s2 - M2) : nz2;
                    const float p3 = ((B3 >> bi) & 1u) ? __expf(s3 - M3) : nz3;
                    l0 += p0; l1 += p1; l2 += p2; l3 += p3;
                    const float4* wp = (const float4*)(wh_sm + ridx * WPAD + dofs);
                    const float4 w0 = wp[0], w1 = wp[1], w2 = wp[2], w3 = wp[3];
                    FMA16(v0, p0, w0, w1, w2, w3)
                    FMA16(v1, p1, w0, w1, w2, w3)
                    FMA16(v2, p2, w0, w1, w2, w3)
                    FMA16(v3, p3, w0, w1, w2, w3)
                }
            }
        }
    }

    // ---- Epilogue: reduce within each 16-lane half (half covers all j) ----
    #pragma unroll
    for (int off = 8; off; off >>= 1) {
        l0 += __shfl_xor_sync(FULLM, l0, off);
        l1 += __shfl_xor_sync(FULLM, l1, off);
        l2 += __shfl_xor_sync(FULLM, l2, off);
        l3 += __shfl_xor_sync(FULLM, l3, off);
    }
    float o0 = 0.f, o1 = 0.f, o2 = 0.f, o3 = 0.f;
    #pragma unroll
    for (int dd = 0; dd < 16; dd++) {
        float s0 = v0[dd], s1 = v1[dd], s2 = v2[dd], s3 = v3[dd];
        #pragma unroll
        for (int off = 8; off; off >>= 1) {
            s0 += __shfl_xor_sync(FULLM, s0, off);
            s1 += __shfl_xor_sync(FULLM, s1, off);
            s2 += __shfl_xor_sync(FULLM, s2, off);
            s3 += __shfl_xor_sync(FULLM, s3, off);
        }
        if (jh == dd) { o0 = s0; o1 = s1; o2 = s2; o3 = s3; }
    }

    const int dcol = hd * Dn + dofs + jh;
    float* op = out + (size_t)(b * Nn + base) * (Hn * Dn) + dcol;
    op[0 * Hn * Dn] = o0 / l0;
    op[1 * Hn * Dn] = o1 / l1;
    op[2 * Hn * Dn] = o2 / l2;
    op[3 * Hn * Dn] = o3 / l3;
}

extern "C" void kernel_launch(void* const* d_in, const int* in_sizes, int n_in,
                              void* d_out, int out_size)
{
    // Bind inputs by element count (robust to metadata ordering)
    const float* h = nullptr; const int* adj = nullptr;
    const float* W = nullptr; const float* a = nullptr;
    for (int i = 0; i < n_in; i++) {
        switch (in_sizes[i]) {
            case 1048576: h   = (const float*)d_in[i]; break;
            case 4194304: adj = (const int*)  d_in[i]; break;
            case 16384:   W   = (const float*)d_in[i]; break;
            case 256:     a   = (const float*)d_in[i]; break;
        }
    }
    float* out = (float*)d_out;

    proj_kernel<<<dim3(Bn, Nn / 16), 128>>>(h, W, a);
    attn_kernel<<<dim3(BH, Nn / 32), 256>>>(adj, out);
}

// round 7
// speedup vs baseline: 2.2050x; 2.2050x over previous
#include <cuda_runtime.h>
#include <cstdint>

// Problem dims (fixed): B=4, N=2048, F_in=128, H=4, D=32
#define Bn 4
#define Nn 2048
#define Fn 128
#define Hn 4
#define Dn 32
#define BH (Bn*Hn)
#define LOG2E 1.4426950408889634f
#define FULLM 0xffffffffu

// Scratch (device globals; no allocation allowed). 16B+ alignment for vector access.
__device__ __align__(256) float g_Wh[BH * Nn * Dn];   // [bh][n][d], tf32-rounded values
__device__ __align__(16)  float g_es[BH * Nn];        // e_src (exact fp32)
__device__ __align__(16)  float g_ed[BH * Nn];        // e_dst (exact fp32)

// -------------------- Kernel A: projection + e_src/e_dst --------------------
// grid (B, N/16), 128 threads (4 warps = 4 heads, lane = d)
__global__ __launch_bounds__(128) void proj_kernel(
    const float* __restrict__ h, const float* __restrict__ W,
    const float* __restrict__ a)
{
    __shared__ __align__(16) float h_sm[16 * Fn];
    const int b  = blockIdx.x;
    const int n0 = blockIdx.y * 16;

    const float4* hsrc = (const float4*)(h + (size_t)(b * Nn + n0) * Fn);
    float4* hdst = (float4*)h_sm;
    #pragma unroll
    for (int r = 0; r < 4; r++) hdst[threadIdx.x + r * 128] = hsrc[threadIdx.x + r * 128];
    __syncthreads();

    const int warp = threadIdx.x >> 5;   // head
    const int lane = threadIdx.x & 31;   // d

    const float* Wp = W + (warp * Fn) * Dn + lane;
    float acc[16];
    #pragma unroll
    for (int n = 0; n < 16; n++) acc[n] = 0.f;

    #pragma unroll 4
    for (int f = 0; f < Fn; f++) {
        float w = __ldg(Wp + f * Dn);
        #pragma unroll
        for (int n = 0; n < 16; n++)
            acc[n] = fmaf(h_sm[n * Fn + f], w, acc[n]);
    }

    const float a_s = __ldg(a + warp * (2 * Dn) + lane);
    const float a_d = __ldg(a + warp * (2 * Dn) + Dn + lane);

    const int bh = b * Hn + warp;
    float* whp = g_Wh + ((size_t)bh * Nn + n0) * Dn + lane;

    #pragma unroll
    for (int n = 0; n < 16; n++) {
        // es/ed from EXACT acc (softmax row-max exactness); store Wh rounded to tf32
        float es = acc[n] * a_s;
        float ed = acc[n] * a_d;
        uint32_t t;
        asm("cvt.rna.tf32.f32 %0, %1;" : "=r"(t) : "f"(acc[n]));
        whp[n * Dn] = __uint_as_float(t);
        #pragma unroll
        for (int off = 16; off; off >>= 1) {
            es += __shfl_xor_sync(FULLM, es, off);
            ed += __shfl_xor_sync(FULLM, ed, off);
        }
        if (lane == 0) {
            g_es[bh * Nn + n0 + n] = es;
            g_ed[bh * Nn + n0 + n] = ed;
        }
    }
}

// -------------------- Kernel B: masked softmax + P@Wh via tf32 MMA --------------------
// 128 threads = 4 warps. Block owns 64 rows (warp: 16 rows). Per (b,h): O = P @ Wh.
// P computed in-register directly in mma A-fragment layout; Wh staged via cp.async.
#define TJc 64            // j per chunk
#define NCH (Nn / TJc)    // 32 chunks
#define WST 40            // wh_sm row stride (floats): tid*8+g bank pattern -> conflict-free

__global__ __launch_bounds__(128, 5) void attn_kernel(
    const int* __restrict__ adj, float* __restrict__ out)
{
    __shared__ __align__(16) float    ed_sm[Nn];            // 8 KB (e_dst * LOG2E)
    __shared__ __align__(16) unsigned mask_sm[64 * 64];     // 16 KB adjacency bits
    __shared__ __align__(16) float    wh_sm[2][TJc * WST];  // 20 KB double buffer

    const int bh = blockIdx.x;
    const int b  = bh >> 2;
    const int hd = bh & 3;
    const int rbase = blockIdx.y * 64;
    const int tid  = threadIdx.x;
    const int warp = tid >> 5;
    const int lane = tid & 31;
    const int g  = lane >> 2;    // groupID (row-within-16 mod 8)
    const int qt = lane & 3;     // threadID_in_group (k / col selector)
    const int wrow = warp * 16;  // warp's local row base (0..63)

    const float* whg = g_Wh + (size_t)bh * Nn * Dn;

    // ---- stage e_dst (scaled to log2 units) ----
    {
        const float4* src = (const float4*)(g_ed + bh * Nn);
        float4* dst = (float4*)ed_sm;
        #pragma unroll
        for (int r = 0; r < Nn / 4 / 128; r++) {
            float4 v = src[tid + r * 128];
            v.x *= LOG2E; v.y *= LOG2E; v.z *= LOG2E; v.w *= LOG2E;
            dst[tid + r * 128] = v;
        }
    }

    // ---- prologue: prefetch Wh chunks 0,1 (overlaps pass 1) ----
    #pragma unroll
    for (int c = 0; c < 2; c++) {
        const float* src = whg + (size_t)(c * TJc) * Dn;
        #pragma unroll
        for (int t = 0; t < 4; t++) {
            int idx = tid + t * 128;
            int row = idx >> 3, c4 = idx & 7;
            uint32_t dp = (uint32_t)__cvta_generic_to_shared(&wh_sm[c][row * WST + c4 * 4]);
            asm volatile("cp.async.ca.shared.global [%0], [%1], 16;"
                         :: "r"(dp), "l"(src + row * Dn + c4 * 4));
        }
        asm volatile("cp.async.commit_group;" ::: "memory");
    }

    __syncthreads();   // ed_sm ready for pass 1

    // ---- Pass 1: pack adjacency bits + exact masked row max ----
    // mask word (r, it*4+c) holds bit L for j = it*128 + L*4 + c
    float esA = 0.f, esB = 0.f, MA = 0.f, MB = 0.f, nzA = 0.f, nzB = 0.f;
    for (int rl = 0; rl < 16; rl++) {
        const int r = rbase + wrow + rl;
        const int* adjr = adj + (size_t)r * Nn;
        float m = -1e30f;
        #pragma unroll
        for (int it = 0; it < 16; it++) {
            uint4 av = __ldg((const uint4*)(adjr + it * 128 + lane * 4));
            float4 ev = *(const float4*)(ed_sm + it * 128 + lane * 4);
            unsigned m0 = __ballot_sync(FULLM, (int)av.x > 0);
            unsigned m1 = __ballot_sync(FULLM, (int)av.y > 0);
            unsigned m2 = __ballot_sync(FULLM, (int)av.z > 0);
            unsigned m3 = __ballot_sync(FULLM, (int)av.w > 0);
            if ((int)av.x > 0) m = fmaxf(m, ev.x);
            if ((int)av.y > 0) m = fmaxf(m, ev.y);
            if ((int)av.z > 0) m = fmaxf(m, ev.z);
            if ((int)av.w > 0) m = fmaxf(m, ev.w);
            if (lane == 0)
                *(uint4*)(mask_sm + (wrow + rl) * 64 + it * 4) = make_uint4(m0, m1, m2, m3);
        }
        #pragma unroll
        for (int off = 16; off; off >>= 1) m = fmaxf(m, __shfl_xor_sync(FULLM, m, off));
        const float es = __ldg(g_es + bh * Nn + r) * LOG2E;
        float M, nz;
        if (m < -9e29f) { M = 0.f; nz = 1.f; }   // empty row -> uniform (matches ref)
        else { float s = es + m; M = fmaxf(s, 0.2f * s); nz = 0.f; }
        if (rl == g)     { esA = es; MA = M; nzA = nz; }
        if (rl == g + 8) { esB = es; MB = M; nzB = nz; }
    }
    __syncthreads();   // mask_sm ready

    // ---- Pass 2: P (in A-fragment layout) @ Wh via mma.m16n8k8 tf32 ----
    float C[4][4];
    #pragma unroll
    for (int nt = 0; nt < 4; nt++)
        #pragma unroll
        for (int k = 0; k < 4; k++) C[nt][k] = 0.f;
    float lA = 0.f, lB = 0.f;

    const int rowA = (wrow + g) * 64;
    const int rowB = (wrow + g + 8) * 64;

    for (int ch = 0; ch < NCH; ch++) {
        asm volatile("cp.async.wait_group 1;" ::: "memory");
        __syncthreads();   // buf[ch&1] ready for everyone

        const int jb = ch * TJc;
        const int wofs = ((jb >> 7) << 2) + qt;
        const unsigned wA = mask_sm[rowA + wofs];
        const unsigned wB = mask_sm[rowB + wofs];
        const int bs = (jb & 64) >> 2;   // 0 or 16
        const float* wbuf = wh_sm[ch & 1];

        #pragma unroll
        for (int ks = 0; ks < 8; ks++) {
            const int j0 = ks * 8;
            const float ed0 = ed_sm[jb + j0 + qt];
            const float ed4 = ed_sm[jb + j0 + qt + 4];
            float s;
            s = esA + ed0; s = fmaxf(s, 0.2f * s);
            const float pA0 = ((wA >> (bs + 2 * ks)) & 1u) ? exp2f(s - MA) : nzA;
            s = esB + ed0; s = fmaxf(s, 0.2f * s);
            const float pB0 = ((wB >> (bs + 2 * ks)) & 1u) ? exp2f(s - MB) : nzB;
            s = esA + ed4; s = fmaxf(s, 0.2f * s);
            const float pA4 = ((wA >> (bs + 2 * ks + 1)) & 1u) ? exp2f(s - MA) : nzA;
            s = esB + ed4; s = fmaxf(s, 0.2f * s);
            const float pB4 = ((wB >> (bs + 2 * ks + 1)) & 1u) ? exp2f(s - MB) : nzB;
            lA += pA0 + pA4;
            lB += pB0 + pB4;
            uint32_t a0, a1, a2, a3;
            asm("cvt.rna.tf32.f32 %0, %1;" : "=r"(a0) : "f"(pA0));
            asm("cvt.rna.tf32.f32 %0, %1;" : "=r"(a1) : "f"(pB0));
            asm("cvt.rna.tf32.f32 %0, %1;" : "=r"(a2) : "f"(pA4));
            asm("cvt.rna.tf32.f32 %0, %1;" : "=r"(a3) : "f"(pB4));
            const float* w0p = wbuf + (j0 + qt) * WST + g;
            const float* w1p = wbuf + (j0 + qt + 4) * WST + g;
            #pragma unroll
            for (int nt = 0; nt < 4; nt++) {
                const uint32_t b0 = __float_as_uint(w0p[nt * 8]);
                const uint32_t b1 = __float_as_uint(w1p[nt * 8]);
                asm volatile(
                    "mma.sync.aligned.m16n8k8.row.col.f32.tf32.tf32.f32 "
                    "{%0,%1,%2,%3}, {%4,%5,%6,%7}, {%8,%9}, {%0,%1,%2,%3};"
                    : "+f"(C[nt][0]), "+f"(C[nt][1]), "+f"(C[nt][2]), "+f"(C[nt][3])
                    : "r"(a0), "r"(a1), "r"(a2), "r"(a3), "r"(b0), "r"(b1));
            }
        }

        __syncthreads();   // all warps done with buf[ch&1]
        const int nc = ch + 2;
        if (nc < NCH) {
            const float* src = whg + (size_t)(nc * TJc) * Dn;
            #pragma unroll
            for (int t = 0; t < 4; t++) {
                int idx = tid + t * 128;
                int row = idx >> 3, c4 = idx & 7;
                uint32_t dp = (uint32_t)__cvta_generic_to_shared(&wh_sm[nc & 1][row * WST + c4 * 4]);
                asm volatile("cp.async.ca.shared.global [%0], [%1], 16;"
                             :: "r"(dp), "l"(src + row * Dn + c4 * 4));
            }
        }
        asm volatile("cp.async.commit_group;" ::: "memory");   // unconditional (may be empty)
    }

    // ---- Epilogue: l over quad (tid 0..3 covers all j residues), normalize, store ----
    #pragma unroll
    for (int off = 1; off < 4; off <<= 1) {
        lA += __shfl_xor_sync(FULLM, lA, off);
        lB += __shfl_xor_sync(FULLM, lB, off);
    }
    const float rlA = 1.f / lA;
    const float rlB = 1.f / lB;
    const int iA = rbase + wrow + g;
    const int iB = iA + 8;
    float* outA = out + (size_t)(b * Nn + iA) * (Hn * Dn) + hd * Dn + 2 * qt;
    float* outB = out + (size_t)(b * Nn + iB) * (Hn * Dn) + hd * Dn + 2 * qt;
    #pragma unroll
    for (int nt = 0; nt < 4; nt++) {
        *(float2*)(outA + nt * 8) = make_float2(C[nt][0] * rlA, C[nt][1] * rlA);
        *(float2*)(outB + nt * 8) = make_float2(C[nt][2] * rlB, C[nt][3] * rlB);
    }
}

extern "C" void kernel_launch(void* const* d_in, const int* in_sizes, int n_in,
                              void* d_out, int out_size)
{
    // Bind inputs by element count (robust to metadata ordering)
    const float* h = nullptr; const int* adj = nullptr;
    const float* W = nullptr; const float* a = nullptr;
    for (int i = 0; i < n_in; i++) {
        switch (in_sizes[i]) {
            case 1048576: h   = (const float*)d_in[i]; break;
            case 4194304: adj = (const int*)  d_in[i]; break;
            case 16384:   W   = (const float*)d_in[i]; break;
            case 256:     a   = (const float*)d_in[i]; break;
        }
    }
    float* out = (float*)d_out;

    proj_kernel<<<dim3(Bn, Nn / 16), 128>>>(h, W, a);
    attn_kernel<<<dim3(BH, Nn / 64), 128>>>(adj, out);
}